// round 1
// baseline (speedup 1.0000x reference)
#include <cuda_runtime.h>
#include <math.h>

#define BB 2
#define SS 1024
#define TT 1024
#define DS 128
#define DT 64
#define H 64
#define LN_EPS 1e-5f

#define TILE_T 8
#define CH 32
#define USTRIDE 65
#define SADSTRIDE 66

// ---------------- scratch (device globals; no allocation allowed) ----------------
__device__ float g_s_ad[BB * SS * H];   // source adapter output
__device__ float g_u[BB * SS * H];      // s_ad @ cW_s
__device__ float g_t_ad[BB * TT * H];   // target adapter output
__device__ float g_a[BB * TT * H];      // t_ad @ cW_t + cb
__device__ float g_sum_u[BB * SS];
__device__ float g_su2[BB * SS];
__device__ float g_sum_a[BB * TT];
__device__ float g_sa2[BB * TT];
__device__ float g_gate[BB * TT];

// ---------------- adapter: ad = relu(LN(x@W1+b1; g,beta)) @ W2 + b2 ----------------
// Also computes proj = ad @ cWpart (+ cb for target), per-row sum/sumsq of proj,
// and (target only) gate = sigmoid(mean(ad)).
template <int DIN, bool IS_TARGET>
__global__ void adapter_kernel(const float* __restrict__ X,
                               const float* __restrict__ W1, const float* __restrict__ b1,
                               const float* __restrict__ g,  const float* __restrict__ beta,
                               const float* __restrict__ W2, const float* __restrict__ b2,
                               const float* __restrict__ cWpart, const float* __restrict__ cb)
{
    __shared__ float sh_x[DIN];
    __shared__ float sh_r[H];
    __shared__ float sh_ad[H];
    __shared__ float sh_red[4];

    const int row = blockIdx.x;
    const int j = threadIdx.x;          // 0..63
    const int wid = j >> 5;

    const float* xrow = X + (size_t)row * DIN;
    sh_x[j] = xrow[j];
    if (DIN == 128) sh_x[j + 64] = xrow[j + 64];
    __syncthreads();

    // layer 1
    float h = b1[j];
#pragma unroll
    for (int k = 0; k < DIN; k++) h = fmaf(sh_x[k], W1[k * H + j], h);

    // LN reduce (sum, sumsq) over 64 lanes (2 warps)
    float s1 = h, s2 = h * h;
#pragma unroll
    for (int o = 16; o; o >>= 1) {
        s1 += __shfl_xor_sync(~0u, s1, o);
        s2 += __shfl_xor_sync(~0u, s2, o);
    }
    if ((j & 31) == 0) { sh_red[wid] = s1; sh_red[2 + wid] = s2; }
    __syncthreads();
    const float m  = (sh_red[0] + sh_red[1]) * (1.f / H);
    const float e2 = (sh_red[2] + sh_red[3]) * (1.f / H);
    const float inv = rsqrtf(e2 - m * m + LN_EPS);
    float r = (h - m) * inv * g[j] + beta[j];
    r = fmaxf(r, 0.f);
    __syncthreads();                    // sh_red reads done before later reuse
    sh_r[j] = r;
    __syncthreads();

    // layer 2
    float ad = b2[j];
#pragma unroll
    for (int k = 0; k < H; k++) ad = fmaf(sh_r[k], W2[k * H + j], ad);

    if (IS_TARGET) {
        g_t_ad[(size_t)row * H + j] = ad;
        float s = ad;
#pragma unroll
        for (int o = 16; o; o >>= 1) s += __shfl_xor_sync(~0u, s, o);
        if ((j & 31) == 0) sh_red[wid] = s;
    } else {
        g_s_ad[(size_t)row * H + j] = ad;
    }
    sh_ad[j] = ad;
    __syncthreads();

    if (IS_TARGET && j == 0) {
        float mt = (sh_red[0] + sh_red[1]) * (1.f / H);
        g_gate[row] = 1.f / (1.f + __expf(-mt));
    }

    // projection: proj = ad @ cWpart (+cb if target)
    float p = IS_TARGET ? cb[j] : 0.f;
#pragma unroll
    for (int k = 0; k < H; k++) p = fmaf(sh_ad[k], cWpart[k * H + j], p);

    if (IS_TARGET) g_a[(size_t)row * H + j] = p;
    else           g_u[(size_t)row * H + j] = p;

    float p1 = p, p2 = p * p;
#pragma unroll
    for (int o = 16; o; o >>= 1) {
        p1 += __shfl_xor_sync(~0u, p1, o);
        p2 += __shfl_xor_sync(~0u, p2, o);
    }
    __syncthreads();                    // gate's sh_red read done before overwrite
    if ((j & 31) == 0) { sh_red[wid] = p1; sh_red[2 + wid] = p2; }
    __syncthreads();
    if (j == 0) {
        if (IS_TARGET) { g_sum_a[row] = sh_red[0] + sh_red[1]; g_sa2[row] = sh_red[2] + sh_red[3]; }
        else           { g_sum_u[row] = sh_red[0] + sh_red[1]; g_su2[row] = sh_red[2] + sh_red[3]; }
    }
}

// ---------------- fused score + softmax + transfer + gate kernel ----------------
// Block: 256 threads = 8 warps; warp <-> one t-row; lanes <-> s within a 32-chunk.
// Per (t,s) pair: LN stats via precomputed sums + dot(a_t, u_s); then per-h relu pass.
__global__ __launch_bounds__(256, 2)
void score_kernel(const float* __restrict__ cg, const float* __restrict__ cbeta,
                  const float* __restrict__ simW, const float* __restrict__ simb,
                  float* __restrict__ out_adapted, float* __restrict__ out_scores)
{
    __shared__ float u_sh[CH * USTRIDE];
    __shared__ float sad_sh[CH * SADSTRIDE];
    __shared__ float cg_sh[H], cbt_sh[H], w_sh[H];

    const int tid = threadIdx.x;
    const int w = tid >> 5, lane = tid & 31;
    const int tglob = blockIdx.x * TILE_T + w;     // global t-row (b*1024 + t)
    const int b = tglob >> 10;
    const int srow0 = b << 10;                     // first s-row of this batch

    if (tid < H) { cg_sh[tid] = cg[tid]; cbt_sh[tid] = cbeta[tid]; w_sh[tid] = simW[tid]; }
    const float simb0 = simb[0];

    // a_t into registers (warp-uniform loads)
    float areg[H];
    const float* arow = g_a + (size_t)tglob * H;
#pragma unroll
    for (int h = 0; h < H; h++) areg[h] = arow[h];
    const float suma = g_sum_a[tglob];
    const float sqa  = g_sa2[tglob];

    float acc0 = 0.f, acc1 = 0.f, sumexp = 0.f;
    float* srow_out = out_scores + (size_t)tglob * SS;

    for (int c = 0; c < SS / CH; c++) {
        __syncthreads();
        // stage u chunk + s_ad chunk (padded strides -> conflict-free reads)
        {
            const float* ub = g_u    + (size_t)(srow0 + c * CH) * H;
            const float* sb = g_s_ad + (size_t)(srow0 + c * CH) * H;
#pragma unroll
            for (int i = tid; i < CH * H; i += 256) {
                int r = i >> 6, cc = i & 63;
                u_sh[r * USTRIDE + cc]     = ub[i];
                sad_sh[r * SADSTRIDE + cc] = sb[i];
            }
        }
        __syncthreads();

        const int sidx = srow0 + c * CH + lane;
        const float su  = g_sum_u[sidx];
        const float squ = g_su2[sidx];
        const float* up = &u_sh[lane * USTRIDE];

        // pass 1: dot(a, u)  -> variance via decomposition
        float dot = 0.f;
#pragma unroll
        for (int h = 0; h < H; h++) dot = fmaf(areg[h], up[h], dot);

        const float m   = (suma + su) * (1.f / H);
        const float e2  = (sqa + 2.f * dot + squ) * (1.f / H);
        const float inv = rsqrtf(e2 - m * m + LN_EPS);
        const float nm  = -m * inv;

        // pass 2: sum_h relu(LN(pre)_h) * simW_h
        float acc = 0.f;
#pragma unroll
        for (int h = 0; h < H; h++) {
            float pre = areg[h] + up[h];
            float z = fmaf(pre, inv, nm);
            float y = fmaf(z, cg_sh[h], cbt_sh[h]);
            acc = fmaf(fmaxf(y, 0.f), w_sh[h], acc);
        }
        const float score = 1.f / (1.f + __expf(-(acc + simb0)));
        srow_out[c * CH + lane] = score;

        // fused softmax (scores in (0,1): no max-subtract needed) + transferred
        const float e = __expf(score);
        sumexp += e;
#pragma unroll
        for (int j = 0; j < CH; j++) {
            float ej = __shfl_sync(~0u, e, j);
            acc0 = fmaf(ej, sad_sh[j * SADSTRIDE + 2 * lane],     acc0);
            acc1 = fmaf(ej, sad_sh[j * SADSTRIDE + 2 * lane + 1], acc1);
        }
    }

#pragma unroll
    for (int o = 16; o; o >>= 1) sumexp += __shfl_xor_sync(~0u, sumexp, o);
    const float rs = 1.f / sumexp;

    const float gt = g_gate[tglob];
    const float* trow = g_t_ad + (size_t)tglob * H;
    const float ta0 = trow[2 * lane], ta1 = trow[2 * lane + 1];
    out_adapted[(size_t)tglob * H + 2 * lane]     = ta0 * (1.f - gt) + acc0 * rs * gt;
    out_adapted[(size_t)tglob * H + 2 * lane + 1] = ta1 * (1.f - gt) + acc1 * rs * gt;
}

// ---------------- launch ----------------
extern "C" void kernel_launch(void* const* d_in, const int* in_sizes, int n_in,
                              void* d_out, int out_size)
{
    (void)in_sizes; (void)n_in; (void)out_size;
    const float* src   = (const float*)d_in[0];
    const float* tgt   = (const float*)d_in[1];
    const float* sW1   = (const float*)d_in[2];
    const float* sb1   = (const float*)d_in[3];
    const float* sg    = (const float*)d_in[4];
    const float* sbeta = (const float*)d_in[5];
    const float* sW2   = (const float*)d_in[6];
    const float* sb2   = (const float*)d_in[7];
    const float* tW1   = (const float*)d_in[8];
    const float* tb1   = (const float*)d_in[9];
    const float* tg    = (const float*)d_in[10];
    const float* tbeta = (const float*)d_in[11];
    const float* tW2   = (const float*)d_in[12];
    const float* tb2   = (const float*)d_in[13];
    const float* cW    = (const float*)d_in[14];
    const float* cb    = (const float*)d_in[15];
    const float* cg    = (const float*)d_in[16];
    const float* cbeta = (const float*)d_in[17];
    const float* simW  = (const float*)d_in[18];
    const float* simb  = (const float*)d_in[19];

    float* out_adapted = (float*)d_out;                    // (B,T,H)
    float* out_scores  = out_adapted + (size_t)BB * TT * H; // (B,T,S)

    // source adapter: cW_s = cW[H:], no cb, no gate
    adapter_kernel<DS, false><<<BB * SS, 64>>>(src, sW1, sb1, sg, sbeta, sW2, sb2,
                                               cW + H * H, nullptr);
    // target adapter: cW_t = cW[:H], +cb, gate
    adapter_kernel<DT, true><<<BB * TT, 64>>>(tgt, tW1, tb1, tg, tbeta, tW2, tb2,
                                              cW, cb);
    // fused score/softmax/transfer
    score_kernel<<<(BB * TT) / TILE_T, 256>>>(cg, cbeta, simW, simb,
                                              out_adapted, out_scores);
}

// round 2
// speedup vs baseline: 1.7300x; 1.7300x over previous
#include <cuda_runtime.h>
#include <math.h>

#define BB 2
#define SS 1024
#define TT 1024
#define DS 128
#define DT 64
#define H 64
#define LN_EPS 1e-5f

#define TILE_T 8
#define CH 32
#define USTRIDE 68   // floats; 68*4B=272B row stride -> float4 reads conflict-free
#define TG 8         // t-rows per transfer block

// ---------------- scratch (device globals; no allocation allowed) ----------------
__device__ float g_s_ad[BB * SS * H];
__device__ float g_u[BB * SS * H];
__device__ float g_t_ad[BB * TT * H];
__device__ float g_a[BB * TT * H];
__device__ float g_sum_u[BB * SS];
__device__ float g_su2[BB * SS];
__device__ float g_sum_a[BB * TT];
__device__ float g_sa2[BB * TT];
__device__ float g_gate[BB * TT];
__device__ float g_sumexp[BB * TT];

// constants for the score kernel (uniform/LDCU path, off the smem crossbar)
__constant__ float c_cg[H];
__constant__ float c_cb[H];
__constant__ float c_w[H];
__constant__ float c_simb[1];

// ---------------- adapter: ad = relu(LN(x@W1+b1; g,beta)) @ W2 + b2 ----------------
// 4 rows per 256-thread block; 64-thread group per row.
template <int DIN, bool IS_TARGET>
__global__ __launch_bounds__(256)
void adapter_kernel(const float* __restrict__ X,
                    const float* __restrict__ W1, const float* __restrict__ b1,
                    const float* __restrict__ g,  const float* __restrict__ beta,
                    const float* __restrict__ W2, const float* __restrict__ b2,
                    const float* __restrict__ cWpart, const float* __restrict__ cb)
{
    __shared__ float sh_x[4][DIN];
    __shared__ float sh_r[4][H];
    __shared__ float sh_ad[4][H];
    __shared__ float sh_red[4][4];

    const int gid = threadIdx.x >> 6;
    const int j = threadIdx.x & 63;
    const int wid = j >> 5;
    const int row = blockIdx.x * 4 + gid;

    const float4* xrow4 = (const float4*)(X + (size_t)row * DIN);
    if (j < DIN / 4) ((float4*)sh_x[gid])[j] = xrow4[j];
    __syncthreads();

    // layer 1 with 4 independent FMA chains
    const float* sx = sh_x[gid];
    float h0 = 0.f, h1 = 0.f, h2 = 0.f, h3 = 0.f;
#pragma unroll
    for (int k = 0; k < DIN; k += 4) {
        h0 = fmaf(sx[k],     W1[(k)     * H + j], h0);
        h1 = fmaf(sx[k + 1], W1[(k + 1) * H + j], h1);
        h2 = fmaf(sx[k + 2], W1[(k + 2) * H + j], h2);
        h3 = fmaf(sx[k + 3], W1[(k + 3) * H + j], h3);
    }
    float h = ((h0 + h1) + (h2 + h3)) + b1[j];

    // LN reduce over 64 lanes (2 warps per group)
    float s1 = h, s2 = h * h;
#pragma unroll
    for (int o = 16; o; o >>= 1) {
        s1 += __shfl_xor_sync(~0u, s1, o);
        s2 += __shfl_xor_sync(~0u, s2, o);
    }
    if ((j & 31) == 0) { sh_red[gid][wid] = s1; sh_red[gid][2 + wid] = s2; }
    __syncthreads();
    const float m   = (sh_red[gid][0] + sh_red[gid][1]) * (1.f / H);
    const float e2  = (sh_red[gid][2] + sh_red[gid][3]) * (1.f / H);
    const float inv = rsqrtf(e2 - m * m + LN_EPS);
    float r = (h - m) * inv * g[j] + beta[j];
    r = fmaxf(r, 0.f);
    __syncthreads();
    sh_r[gid][j] = r;
    __syncthreads();

    // layer 2 (4 chains)
    const float* sr = sh_r[gid];
    float a0 = 0.f, a1 = 0.f, a2 = 0.f, a3 = 0.f;
#pragma unroll
    for (int k = 0; k < H; k += 4) {
        a0 = fmaf(sr[k],     W2[(k)     * H + j], a0);
        a1 = fmaf(sr[k + 1], W2[(k + 1) * H + j], a1);
        a2 = fmaf(sr[k + 2], W2[(k + 2) * H + j], a2);
        a3 = fmaf(sr[k + 3], W2[(k + 3) * H + j], a3);
    }
    float ad = ((a0 + a1) + (a2 + a3)) + b2[j];

    if (IS_TARGET) {
        g_t_ad[(size_t)row * H + j] = ad;
        float s = ad;
#pragma unroll
        for (int o = 16; o; o >>= 1) s += __shfl_xor_sync(~0u, s, o);
        if ((j & 31) == 0) sh_red[gid][wid] = s;
    } else {
        g_s_ad[(size_t)row * H + j] = ad;
    }
    sh_ad[gid][j] = ad;
    __syncthreads();

    if (IS_TARGET && j == 0) {
        float mt = (sh_red[gid][0] + sh_red[gid][1]) * (1.f / H);
        g_gate[row] = 1.f / (1.f + __expf(-mt));
    }

    // projection: proj = ad @ cWpart (+cb if target)
    const float* sa = sh_ad[gid];
    float p0 = IS_TARGET ? cb[j] : 0.f, p1k = 0.f, p2k = 0.f, p3k = 0.f;
#pragma unroll
    for (int k = 0; k < H; k += 4) {
        p0  = fmaf(sa[k],     cWpart[(k)     * H + j], p0);
        p1k = fmaf(sa[k + 1], cWpart[(k + 1) * H + j], p1k);
        p2k = fmaf(sa[k + 2], cWpart[(k + 2) * H + j], p2k);
        p3k = fmaf(sa[k + 3], cWpart[(k + 3) * H + j], p3k);
    }
    float p = ((p0 + p1k) + (p2k + p3k));

    if (IS_TARGET) g_a[(size_t)row * H + j] = p;
    else           g_u[(size_t)row * H + j] = p;

    float q1 = p, q2 = p * p;
#pragma unroll
    for (int o = 16; o; o >>= 1) {
        q1 += __shfl_xor_sync(~0u, q1, o);
        q2 += __shfl_xor_sync(~0u, q2, o);
    }
    __syncthreads();
    if ((j & 31) == 0) { sh_red[gid][wid] = q1; sh_red[gid][2 + wid] = q2; }
    __syncthreads();
    if (j == 0) {
        if (IS_TARGET) { g_sum_a[row] = sh_red[gid][0] + sh_red[gid][1]; g_sa2[row] = sh_red[gid][2] + sh_red[gid][3]; }
        else           { g_sum_u[row] = sh_red[gid][0] + sh_red[gid][1]; g_su2[row] = sh_red[gid][2] + sh_red[gid][3]; }
    }
}

// ---------------- score kernel: warp<->t, lanes<->s chunk ----------------
__global__ __launch_bounds__(256, 2)
void score_kernel(float* __restrict__ out_scores)
{
    __shared__ __align__(16) float u_sh[CH * USTRIDE];

    const int tid = threadIdx.x;
    const int lane = tid & 31;
    const int w = tid >> 5;
    const int tglob = blockIdx.x * TILE_T + w;
    const int b = tglob >> 10;
    const int srow0 = b << 10;

    // a_t (warp-uniform) into registers
    float areg[H];
    {
        const float4* arow4 = (const float4*)(g_a + (size_t)tglob * H);
#pragma unroll
        for (int i = 0; i < H / 4; i++) {
            float4 v = arow4[i];
            areg[4 * i] = v.x; areg[4 * i + 1] = v.y;
            areg[4 * i + 2] = v.z; areg[4 * i + 3] = v.w;
        }
    }
    const float suma = g_sum_a[tglob];
    const float sqa  = g_sa2[tglob];
    const float simb0 = c_simb[0];

    float sumexp = 0.f;
    float* srow_out = out_scores + (size_t)tglob * SS;

    for (int c = 0; c < SS / CH; c++) {
        __syncthreads();
        {   // stage u chunk as float4s into padded tile
            const float4* ub4 = (const float4*)(g_u + (size_t)(srow0 + c * CH) * H);
#pragma unroll
            for (int f = tid; f < CH * H / 4; f += 256) {
                int r = f >> 4, q = f & 15;
                *(float4*)&u_sh[r * USTRIDE + q * 4] = ub4[f];
            }
        }
        __syncthreads();

        const int sidx = srow0 + c * CH + lane;
        const float su  = g_sum_u[sidx];
        const float squ = g_su2[sidx];
        const float4* up4 = (const float4*)&u_sh[lane * USTRIDE];

        // pass 1: dot(a,u) with 4 chains
        float d0 = 0.f, d1 = 0.f, d2 = 0.f, d3 = 0.f;
#pragma unroll
        for (int i = 0; i < 16; i++) {
            float4 u4 = up4[i];
            d0 = fmaf(areg[4 * i],     u4.x, d0);
            d1 = fmaf(areg[4 * i + 1], u4.y, d1);
            d2 = fmaf(areg[4 * i + 2], u4.z, d2);
            d3 = fmaf(areg[4 * i + 3], u4.w, d3);
        }
        const float dot = (d0 + d1) + (d2 + d3);
        const float m   = (suma + su) * (1.f / H);
        const float e2  = (sqa + 2.f * dot + squ) * (1.f / H);
        const float inv = rsqrtf(e2 - m * m + LN_EPS);
        const float nm  = -m * inv;

        // pass 2: sum_h relu(LN)*w, constants via __constant__ (uniform port)
        float a0 = 0.f, a1 = 0.f, a2 = 0.f, a3 = 0.f;
#pragma unroll
        for (int i = 0; i < 16; i++) {
            float4 u4 = up4[i];
            float z0 = fmaf(areg[4 * i]     + u4.x, inv, nm);
            float z1 = fmaf(areg[4 * i + 1] + u4.y, inv, nm);
            float z2 = fmaf(areg[4 * i + 2] + u4.z, inv, nm);
            float z3 = fmaf(areg[4 * i + 3] + u4.w, inv, nm);
            a0 = fmaf(fmaxf(fmaf(z0, c_cg[4 * i],     c_cb[4 * i]),     0.f), c_w[4 * i],     a0);
            a1 = fmaf(fmaxf(fmaf(z1, c_cg[4 * i + 1], c_cb[4 * i + 1]), 0.f), c_w[4 * i + 1], a1);
            a2 = fmaf(fmaxf(fmaf(z2, c_cg[4 * i + 2], c_cb[4 * i + 2]), 0.f), c_w[4 * i + 2], a2);
            a3 = fmaf(fmaxf(fmaf(z3, c_cg[4 * i + 3], c_cb[4 * i + 3]), 0.f), c_w[4 * i + 3], a3);
        }
        const float acc = (a0 + a1) + (a2 + a3);
        const float score = 1.f / (1.f + __expf(-(acc + simb0)));
        srow_out[c * CH + lane] = score;
        sumexp += __expf(score);
    }

#pragma unroll
    for (int o = 16; o; o >>= 1) sumexp += __shfl_xor_sync(~0u, sumexp, o);
    if (lane == 0) g_sumexp[tglob] = sumexp;
}

// ---------------- transfer kernel: adapted = t_ad*(1-g) + (attn @ s_ad)*g ----------------
// Block: 8 warps, TG=8 t-rows. Warp w covers s in [w*128,(w+1)*128); 8 t amortize s_ad reads.
__global__ __launch_bounds__(256)
void transfer_kernel(const float* __restrict__ scores, float* __restrict__ out_adapted)
{
    __shared__ __align__(16) float sh[4096];  // phase1: e[8w][32j][8t] (2048); phase2: partials (4096)

    const int tid = threadIdx.x;
    const int w = tid >> 5, lane = tid & 31;
    const int tbase = blockIdx.x * TG;
    const int b = tbase >> 10;
    const int srow0 = b << 10;

    float2 acc[TG];
#pragma unroll
    for (int t = 0; t < TG; t++) acc[t] = make_float2(0.f, 0.f);

    float* e_sh = sh + w * 256;  // [32 j][8 t]

    for (int c = 0; c < 4; c++) {
        const int sloc0 = w * 128 + c * 32;   // s within batch, this warp's range

        float ev[TG];
#pragma unroll
        for (int t = 0; t < TG; t++)
            ev[t] = __expf(scores[(size_t)(tbase + t) * SS + sloc0 + lane]);
        __syncwarp();
        *(float4*)&e_sh[lane * 8]     = make_float4(ev[0], ev[1], ev[2], ev[3]);
        *(float4*)&e_sh[lane * 8 + 4] = make_float4(ev[4], ev[5], ev[6], ev[7]);
        __syncwarp();

#pragma unroll 4
        for (int j = 0; j < 32; j++) {
            const float2 v = *(const float2*)(g_s_ad + (size_t)(srow0 + sloc0 + j) * H + 2 * lane);
            const float4 e0 = *(const float4*)&e_sh[j * 8];
            const float4 e1 = *(const float4*)&e_sh[j * 8 + 4];
            acc[0].x = fmaf(e0.x, v.x, acc[0].x); acc[0].y = fmaf(e0.x, v.y, acc[0].y);
            acc[1].x = fmaf(e0.y, v.x, acc[1].x); acc[1].y = fmaf(e0.y, v.y, acc[1].y);
            acc[2].x = fmaf(e0.z, v.x, acc[2].x); acc[2].y = fmaf(e0.z, v.y, acc[2].y);
            acc[3].x = fmaf(e0.w, v.x, acc[3].x); acc[3].y = fmaf(e0.w, v.y, acc[3].y);
            acc[4].x = fmaf(e1.x, v.x, acc[4].x); acc[4].y = fmaf(e1.x, v.y, acc[4].y);
            acc[5].x = fmaf(e1.y, v.x, acc[5].x); acc[5].y = fmaf(e1.y, v.y, acc[5].y);
            acc[6].x = fmaf(e1.z, v.x, acc[6].x); acc[6].y = fmaf(e1.z, v.y, acc[6].y);
            acc[7].x = fmaf(e1.w, v.x, acc[7].x); acc[7].y = fmaf(e1.w, v.y, acc[7].y);
        }
    }

    __syncthreads();   // all warps done with e regions
#pragma unroll
    for (int t = 0; t < TG; t++)
        *(float2*)&sh[w * 512 + t * 64 + 2 * lane] = acc[t];
    __syncthreads();

    // reduce across 8 warps: this thread handles (t = tbase + w, h-pair = lane)
    float2 s = make_float2(0.f, 0.f);
#pragma unroll
    for (int ww = 0; ww < 8; ww++) {
        float2 p = *(float2*)&sh[ww * 512 + w * 64 + 2 * lane];
        s.x += p.x; s.y += p.y;
    }
    const int t = tbase + w;
    const float rs = 1.f / g_sumexp[t];
    const float gt = g_gate[t];
    const float2 ta = *(const float2*)&g_t_ad[(size_t)t * H + 2 * lane];
    float2 o;
    o.x = ta.x * (1.f - gt) + s.x * rs * gt;
    o.y = ta.y * (1.f - gt) + s.y * rs * gt;
    *(float2*)&out_adapted[(size_t)t * H + 2 * lane] = o;
}

// ---------------- launch ----------------
extern "C" void kernel_launch(void* const* d_in, const int* in_sizes, int n_in,
                              void* d_out, int out_size)
{
    (void)in_sizes; (void)n_in; (void)out_size;
    const float* src   = (const float*)d_in[0];
    const float* tgt   = (const float*)d_in[1];
    const float* sW1   = (const float*)d_in[2];
    const float* sb1   = (const float*)d_in[3];
    const float* sg    = (const float*)d_in[4];
    const float* sbeta = (const float*)d_in[5];
    const float* sW2   = (const float*)d_in[6];
    const float* sb2   = (const float*)d_in[7];
    const float* tW1   = (const float*)d_in[8];
    const float* tb1   = (const float*)d_in[9];
    const float* tg    = (const float*)d_in[10];
    const float* tbeta = (const float*)d_in[11];
    const float* tW2   = (const float*)d_in[12];
    const float* tb2   = (const float*)d_in[13];
    const float* cW    = (const float*)d_in[14];
    const float* cb    = (const float*)d_in[15];
    const float* cg    = (const float*)d_in[16];
    const float* cbeta = (const float*)d_in[17];
    const float* simW  = (const float*)d_in[18];
    const float* simb  = (const float*)d_in[19];

    float* out_adapted = (float*)d_out;                      // (B,T,H)
    float* out_scores  = out_adapted + (size_t)BB * TT * H;  // (B,T,S)

    // constants for score kernel (D2D copies; graph-capturable memcpy nodes)
    cudaMemcpyToSymbolAsync(c_cg,   cg,    H * sizeof(float), 0, cudaMemcpyDeviceToDevice, 0);
    cudaMemcpyToSymbolAsync(c_cb,   cbeta, H * sizeof(float), 0, cudaMemcpyDeviceToDevice, 0);
    cudaMemcpyToSymbolAsync(c_w,    simW,  H * sizeof(float), 0, cudaMemcpyDeviceToDevice, 0);
    cudaMemcpyToSymbolAsync(c_simb, simb,  sizeof(float),     0, cudaMemcpyDeviceToDevice, 0);

    adapter_kernel<DS, false><<<BB * SS / 4, 256>>>(src, sW1, sb1, sg, sbeta, sW2, sb2,
                                                    cW + H * H, nullptr);
    adapter_kernel<DT, true><<<BB * TT / 4, 256>>>(tgt, tW1, tb1, tg, tbeta, tW2, tb2,
                                                   cW, cb);
    score_kernel<<<(BB * TT) / TILE_T, 256>>>(out_scores);
    transfer_kernel<<<(BB * TT) / TG, 256>>>(out_scores, out_adapted);
}

// round 3
// speedup vs baseline: 1.8297x; 1.0576x over previous
#include <cuda_runtime.h>
#include <math.h>

#define BB 2
#define SS 1024
#define TT 1024
#define DS 128
#define DT 64
#define H 64
#define LN_EPS 1e-5f

#define TILE_T 8
#define CH 32
#define USTRIDE 68   // floats; 272B row stride, 16B-aligned rows, conflict-free float4
#define TG 4         // t-rows per transfer block

typedef unsigned long long ull;

__device__ __forceinline__ ull fma2(ull a, ull b, ull c) {
    ull d; asm("fma.rn.f32x2 %0,%1,%2,%3;" : "=l"(d) : "l"(a), "l"(b), "l"(c)); return d;
}
__device__ __forceinline__ ull add2(ull a, ull b) {
    ull d; asm("add.rn.f32x2 %0,%1,%2;" : "=l"(d) : "l"(a), "l"(b)); return d;
}
__device__ __forceinline__ ull pack2(float lo, float hi) {
    ull d; asm("mov.b64 %0,{%1,%2};" : "=l"(d) : "f"(lo), "f"(hi)); return d;
}
__device__ __forceinline__ float2 unpack2(ull v) {
    float2 r; asm("mov.b64 {%0,%1},%2;" : "=f"(r.x), "=f"(r.y) : "l"(v)); return r;
}

// ---------------- scratch ----------------
__device__ float g_s_ad[BB * SS * H];
__device__ float g_u[BB * SS * H];
__device__ float g_t_ad[BB * TT * H];
__device__ float g_a[BB * TT * H];
__device__ float g_sum_u[BB * SS];
__device__ float g_su2[BB * SS];
__device__ float g_sum_a[BB * TT];
__device__ float g_sa2[BB * TT];
__device__ float g_gate[BB * TT];
__device__ float g_sumexp[BB * TT];

__constant__ float c_cg[H];
__constant__ float c_cb[H];
__constant__ float c_w[H];
__constant__ float c_simb[1];

// ---------------- adapter ----------------
template <int DIN, bool IS_TARGET>
__global__ __launch_bounds__(256)
void adapter_kernel(const float* __restrict__ X,
                    const float* __restrict__ W1, const float* __restrict__ b1,
                    const float* __restrict__ g,  const float* __restrict__ beta,
                    const float* __restrict__ W2, const float* __restrict__ b2,
                    const float* __restrict__ cWpart, const float* __restrict__ cb)
{
    __shared__ float sh_x[4][DIN];
    __shared__ float sh_r[4][H];
    __shared__ float sh_ad[4][H];
    __shared__ float sh_red[4][4];

    const int gid = threadIdx.x >> 6;
    const int j = threadIdx.x & 63;
    const int wid = j >> 5;
    const int row = blockIdx.x * 4 + gid;

    const float4* xrow4 = (const float4*)(X + (size_t)row * DIN);
    if (j < DIN / 4) ((float4*)sh_x[gid])[j] = xrow4[j];
    __syncthreads();

    const float* sx = sh_x[gid];
    float h0 = 0.f, h1 = 0.f, h2 = 0.f, h3 = 0.f;
#pragma unroll
    for (int k = 0; k < DIN; k += 4) {
        h0 = fmaf(sx[k],     W1[(k)     * H + j], h0);
        h1 = fmaf(sx[k + 1], W1[(k + 1) * H + j], h1);
        h2 = fmaf(sx[k + 2], W1[(k + 2) * H + j], h2);
        h3 = fmaf(sx[k + 3], W1[(k + 3) * H + j], h3);
    }
    float h = ((h0 + h1) + (h2 + h3)) + b1[j];

    float s1 = h, s2 = h * h;
#pragma unroll
    for (int o = 16; o; o >>= 1) {
        s1 += __shfl_xor_sync(~0u, s1, o);
        s2 += __shfl_xor_sync(~0u, s2, o);
    }
    if ((j & 31) == 0) { sh_red[gid][wid] = s1; sh_red[gid][2 + wid] = s2; }
    __syncthreads();
    const float m   = (sh_red[gid][0] + sh_red[gid][1]) * (1.f / H);
    const float e2  = (sh_red[gid][2] + sh_red[gid][3]) * (1.f / H);
    const float inv = rsqrtf(e2 - m * m + LN_EPS);
    float r = (h - m) * inv * g[j] + beta[j];
    r = fmaxf(r, 0.f);
    __syncthreads();
    sh_r[gid][j] = r;
    __syncthreads();

    const float* sr = sh_r[gid];
    float a0 = 0.f, a1 = 0.f, a2v = 0.f, a3 = 0.f;
#pragma unroll
    for (int k = 0; k < H; k += 4) {
        a0  = fmaf(sr[k],     W2[(k)     * H + j], a0);
        a1  = fmaf(sr[k + 1], W2[(k + 1) * H + j], a1);
        a2v = fmaf(sr[k + 2], W2[(k + 2) * H + j], a2v);
        a3  = fmaf(sr[k + 3], W2[(k + 3) * H + j], a3);
    }
    float ad = ((a0 + a1) + (a2v + a3)) + b2[j];

    if (IS_TARGET) {
        g_t_ad[(size_t)row * H + j] = ad;
        float s = ad;
#pragma unroll
        for (int o = 16; o; o >>= 1) s += __shfl_xor_sync(~0u, s, o);
        if ((j & 31) == 0) sh_red[gid][wid] = s;
    } else {
        g_s_ad[(size_t)row * H + j] = ad;
    }
    sh_ad[gid][j] = ad;
    __syncthreads();

    if (IS_TARGET && j == 0) {
        float mt = (sh_red[gid][0] + sh_red[gid][1]) * (1.f / H);
        g_gate[row] = 1.f / (1.f + __expf(-mt));
    }

    const float* sa = sh_ad[gid];
    float p0 = IS_TARGET ? cb[j] : 0.f, p1k = 0.f, p2k = 0.f, p3k = 0.f;
#pragma unroll
    for (int k = 0; k < H; k += 4) {
        p0  = fmaf(sa[k],     cWpart[(k)     * H + j], p0);
        p1k = fmaf(sa[k + 1], cWpart[(k + 1) * H + j], p1k);
        p2k = fmaf(sa[k + 2], cWpart[(k + 2) * H + j], p2k);
        p3k = fmaf(sa[k + 3], cWpart[(k + 3) * H + j], p3k);
    }
    float p = ((p0 + p1k) + (p2k + p3k));

    if (IS_TARGET) g_a[(size_t)row * H + j] = p;
    else           g_u[(size_t)row * H + j] = p;

    float q1 = p, q2 = p * p;
#pragma unroll
    for (int o = 16; o; o >>= 1) {
        q1 += __shfl_xor_sync(~0u, q1, o);
        q2 += __shfl_xor_sync(~0u, q2, o);
    }
    __syncthreads();
    if ((j & 31) == 0) { sh_red[gid][wid] = q1; sh_red[gid][2 + wid] = q2; }
    __syncthreads();
    if (j == 0) {
        if (IS_TARGET) { g_sum_a[row] = sh_red[gid][0] + sh_red[gid][1]; g_sa2[row] = sh_red[gid][2] + sh_red[gid][3]; }
        else           { g_sum_u[row] = sh_red[gid][0] + sh_red[gid][1]; g_su2[row] = sh_red[gid][2] + sh_red[gid][3]; }
    }
}

// ---------------- score kernel (packed f32x2 math) ----------------
__global__ __launch_bounds__(256, 2)
void score_kernel(float* __restrict__ out_scores)
{
    __shared__ __align__(16) float u_sh[CH * USTRIDE];

    const int tid = threadIdx.x;
    const int lane = tid & 31;
    const int w = tid >> 5;
    const int tglob = blockIdx.x * TILE_T + w;
    const int b = tglob >> 10;
    const int srow0 = b << 10;

    // a_t packed as 32 x f32x2 pairs (LDG.128 -> two ulls each)
    ull a2[H / 2];
    {
        const ulonglong2* arow = (const ulonglong2*)(g_a + (size_t)tglob * H);
#pragma unroll
        for (int i = 0; i < H / 4; i++) {
            ulonglong2 v = arow[i];
            a2[2 * i] = v.x; a2[2 * i + 1] = v.y;
        }
    }
    const float suma = g_sum_a[tglob];
    const float sqa  = g_sa2[tglob];
    const float simb0 = c_simb[0];

    float sumexp = 0.f;
    float* srow_out = out_scores + (size_t)tglob * SS;

    for (int c = 0; c < SS / CH; c++) {
        __syncthreads();
        {
            const float4* ub4 = (const float4*)(g_u + (size_t)(srow0 + c * CH) * H);
#pragma unroll
            for (int f = tid; f < CH * H / 4; f += 256) {
                int r = f >> 4, q = f & 15;
                *(float4*)&u_sh[r * USTRIDE + q * 4] = ub4[f];
            }
        }
        __syncthreads();

        const int sidx = srow0 + c * CH + lane;
        const float su  = g_sum_u[sidx];
        const float squ = g_su2[sidx];
        const ulonglong2* up2 = (const ulonglong2*)&u_sh[lane * USTRIDE];

        // pass 1: dot(a,u) packed, 4 chains
        ull d0 = 0ull, d1 = 0ull, d2 = 0ull, d3 = 0ull;
#pragma unroll
        for (int i = 0; i < H / 4; i += 2) {
            ulonglong2 ua = up2[i];
            ulonglong2 ubb = up2[i + 1];
            d0 = fma2(a2[2 * i],     ua.x,  d0);
            d1 = fma2(a2[2 * i + 1], ua.y,  d1);
            d2 = fma2(a2[2 * i + 2], ubb.x, d2);
            d3 = fma2(a2[2 * i + 3], ubb.y, d3);
        }
        float2 f0 = unpack2(d0), f1 = unpack2(d1), f2 = unpack2(d2), f3 = unpack2(d3);
        const float dot = ((f0.x + f0.y) + (f1.x + f1.y)) + ((f2.x + f2.y) + (f3.x + f3.y));

        const float m   = (suma + su) * (1.f / H);
        const float e2  = (sqa + 2.f * dot + squ) * (1.f / H);
        const float inv = rsqrtf(e2 - m * m + LN_EPS);
        const float nm  = -m * inv;
        const ull inv2 = pack2(inv, inv);
        const ull nm2  = pack2(nm, nm);

        // pass 2: packed pre/z, scalar relu-weight stage
        float acc0 = 0.f, acc1 = 0.f, acc2 = 0.f, acc3 = 0.f;
#pragma unroll
        for (int i = 0; i < H / 4; i++) {
            ulonglong2 uu = up2[i];
            ull p0 = add2(a2[2 * i],     uu.x);
            ull p1 = add2(a2[2 * i + 1], uu.y);
            ull z0 = fma2(p0, inv2, nm2);
            ull z1 = fma2(p1, inv2, nm2);
            float2 za = unpack2(z0), zb = unpack2(z1);
            acc0 = fmaf(fmaxf(fmaf(za.x, c_cg[4 * i],     c_cb[4 * i]),     0.f), c_w[4 * i],     acc0);
            acc1 = fmaf(fmaxf(fmaf(za.y, c_cg[4 * i + 1], c_cb[4 * i + 1]), 0.f), c_w[4 * i + 1], acc1);
            acc2 = fmaf(fmaxf(fmaf(zb.x, c_cg[4 * i + 2], c_cb[4 * i + 2]), 0.f), c_w[4 * i + 2], acc2);
            acc3 = fmaf(fmaxf(fmaf(zb.y, c_cg[4 * i + 3], c_cb[4 * i + 3]), 0.f), c_w[4 * i + 3], acc3);
        }
        const float acc = (acc0 + acc1) + (acc2 + acc3);
        const float score = 1.f / (1.f + __expf(-(acc + simb0)));
        srow_out[c * CH + lane] = score;
        sumexp += __expf(score);
    }

#pragma unroll
    for (int o = 16; o; o >>= 1) sumexp += __shfl_xor_sync(~0u, sumexp, o);
    if (lane == 0) g_sumexp[tglob] = sumexp;
}

// ---------------- transfer: TG=4 t-rows per block, 512 blocks ----------------
__global__ __launch_bounds__(256)
void transfer_kernel(const float* __restrict__ scores, float* __restrict__ out_adapted)
{
    __shared__ __align__(16) float sh[2048];  // phase1: e[8w][32j][4t]=1024; phase2: partials 8w*4t*64h=2048

    const int tid = threadIdx.x;
    const int w = tid >> 5, lane = tid & 31;
    const int tbase = blockIdx.x * TG;
    const int b = tbase >> 10;
    const int srow0 = b << 10;

    float2 acc[TG];
#pragma unroll
    for (int t = 0; t < TG; t++) acc[t] = make_float2(0.f, 0.f);

    float* e_sh = sh + w * 128;  // [32 j][4 t]

    for (int c = 0; c < 4; c++) {
        const int sloc0 = w * 128 + c * 32;

        float ev[TG];
#pragma unroll
        for (int t = 0; t < TG; t++)
            ev[t] = __expf(scores[(size_t)(tbase + t) * SS + sloc0 + lane]);
        __syncwarp();
        *(float4*)&e_sh[lane * 4] = make_float4(ev[0], ev[1], ev[2], ev[3]);
        __syncwarp();

#pragma unroll 8
        for (int j = 0; j < 32; j++) {
            const float2 v = *(const float2*)(g_s_ad + (size_t)(srow0 + sloc0 + j) * H + 2 * lane);
            const float4 e = *(const float4*)&e_sh[j * 4];
            acc[0].x = fmaf(e.x, v.x, acc[0].x); acc[0].y = fmaf(e.x, v.y, acc[0].y);
            acc[1].x = fmaf(e.y, v.x, acc[1].x); acc[1].y = fmaf(e.y, v.y, acc[1].y);
            acc[2].x = fmaf(e.z, v.x, acc[2].x); acc[2].y = fmaf(e.z, v.y, acc[2].y);
            acc[3].x = fmaf(e.w, v.x, acc[3].x); acc[3].y = fmaf(e.w, v.y, acc[3].y);
        }
        __syncwarp();
    }

    __syncthreads();
#pragma unroll
    for (int t = 0; t < TG; t++)
        *(float2*)&sh[w * 256 + t * 64 + 2 * lane] = acc[t];
    __syncthreads();

    // combine: tid -> (t = tid>>6, h = tid&63)
    const int t = tid >> 6;
    const int hh = tid & 63;
    float s = 0.f;
#pragma unroll
    for (int ww = 0; ww < 8; ww++) s += sh[ww * 256 + t * 64 + hh];

    const int tg = tbase + t;
    const float rs = 1.f / g_sumexp[tg];
    const float gt = g_gate[tg];
    const float ta = g_t_ad[(size_t)tg * H + hh];
    out_adapted[(size_t)tg * H + hh] = ta * (1.f - gt) + s * rs * gt;
}

// ---------------- launch ----------------
extern "C" void kernel_launch(void* const* d_in, const int* in_sizes, int n_in,
                              void* d_out, int out_size)
{
    (void)in_sizes; (void)n_in; (void)out_size;
    const float* src   = (const float*)d_in[0];
    const float* tgt   = (const float*)d_in[1];
    const float* sW1   = (const float*)d_in[2];
    const float* sb1   = (const float*)d_in[3];
    const float* sg    = (const float*)d_in[4];
    const float* sbeta = (const float*)d_in[5];
    const float* sW2   = (const float*)d_in[6];
    const float* sb2   = (const float*)d_in[7];
    const float* tW1   = (const float*)d_in[8];
    const float* tb1   = (const float*)d_in[9];
    const float* tg    = (const float*)d_in[10];
    const float* tbeta = (const float*)d_in[11];
    const float* tW2   = (const float*)d_in[12];
    const float* tb2   = (const float*)d_in[13];
    const float* cW    = (const float*)d_in[14];
    const float* cb    = (const float*)d_in[15];
    const float* cg    = (const float*)d_in[16];
    const float* cbeta = (const float*)d_in[17];
    const float* simW  = (const float*)d_in[18];
    const float* simb  = (const float*)d_in[19];

    float* out_adapted = (float*)d_out;                      // (B,T,H)
    float* out_scores  = out_adapted + (size_t)BB * TT * H;  // (B,T,S)

    cudaMemcpyToSymbolAsync(c_cg,   cg,    H * sizeof(float), 0, cudaMemcpyDeviceToDevice, 0);
    cudaMemcpyToSymbolAsync(c_cb,   cbeta, H * sizeof(float), 0, cudaMemcpyDeviceToDevice, 0);
    cudaMemcpyToSymbolAsync(c_w,    simW,  H * sizeof(float), 0, cudaMemcpyDeviceToDevice, 0);
    cudaMemcpyToSymbolAsync(c_simb, simb,  sizeof(float),     0, cudaMemcpyDeviceToDevice, 0);

    adapter_kernel<DS, false><<<BB * SS / 4, 256>>>(src, sW1, sb1, sg, sbeta, sW2, sb2,
                                                    cW + H * H, nullptr);
    adapter_kernel<DT, true><<<BB * TT / 4, 256>>>(tgt, tW1, tb1, tg, tbeta, tW2, tb2,
                                                   cW, cb);
    score_kernel<<<(BB * TT) / TILE_T, 256>>>(out_scores);
    transfer_kernel<<<(BB * TT) / TG, 256>>>(out_scores, out_adapted);
}

// round 4
// speedup vs baseline: 2.2537x; 1.2317x over previous
#include <cuda_runtime.h>
#include <math.h>

#define BB 2
#define SS 1024
#define TT 1024
#define DS 128
#define DT 64
#define H 64
#define LN_EPS 1e-5f

#define TILE_T 8
#define CH 32
#define USTRIDE 68   // floats; 272B row stride, 16B-aligned, conflict-free 16B reads
#define TTG 8        // t-rows per transfer block

typedef unsigned long long ull;

__device__ __forceinline__ ull fma2(ull a, ull b, ull c) {
    ull d; asm("fma.rn.f32x2 %0,%1,%2,%3;" : "=l"(d) : "l"(a), "l"(b), "l"(c)); return d;
}
__device__ __forceinline__ ull add2(ull a, ull b) {
    ull d; asm("add.rn.f32x2 %0,%1,%2;" : "=l"(d) : "l"(a), "l"(b)); return d;
}
__device__ __forceinline__ ull pack2(float lo, float hi) {
    ull d; asm("mov.b64 %0,{%1,%2};" : "=l"(d) : "f"(lo), "f"(hi)); return d;
}
__device__ __forceinline__ float2 unpack2(ull v) {
    float2 r; asm("mov.b64 {%0,%1},%2;" : "=f"(r.x), "=f"(r.y) : "l"(v)); return r;
}
__device__ __forceinline__ void cp16(void* smem_dst, const void* gsrc) {
    unsigned sa = (unsigned)__cvta_generic_to_shared(smem_dst);
    asm volatile("cp.async.cg.shared.global [%0], [%1], 16;" :: "r"(sa), "l"(gsrc));
}

// ---------------- scratch ----------------
__device__ float g_s_ad[BB * SS * H];
__device__ float g_u[BB * SS * H];
__device__ float g_t_ad[BB * TT * H];
__device__ float g_a[BB * TT * H];
__device__ float g_sum_u[BB * SS];
__device__ float g_su2[BB * SS];
__device__ float g_sum_a[BB * TT];
__device__ float g_sa2[BB * TT];
__device__ float g_gate[BB * TT];
__device__ float g_sumexp[BB * TT];

__constant__ float c_cg[H];
__constant__ float c_cb[H];
__constant__ float c_w[H];
__constant__ float c_simb[1];

// ---------------- adapter ----------------
template <int DIN, bool IS_TARGET>
__global__ __launch_bounds__(256)
void adapter_kernel(const float* __restrict__ X,
                    const float* __restrict__ W1, const float* __restrict__ b1,
                    const float* __restrict__ g,  const float* __restrict__ beta,
                    const float* __restrict__ W2, const float* __restrict__ b2,
                    const float* __restrict__ cWpart, const float* __restrict__ cb)
{
    __shared__ float sh_x[4][DIN];
    __shared__ float sh_r[4][H];
    __shared__ float sh_ad[4][H];
    __shared__ float sh_red[4][4];

    const int gid = threadIdx.x >> 6;
    const int j = threadIdx.x & 63;
    const int wid = j >> 5;
    const int row = blockIdx.x * 4 + gid;

    const float4* xrow4 = (const float4*)(X + (size_t)row * DIN);
    if (j < DIN / 4) ((float4*)sh_x[gid])[j] = xrow4[j];
    __syncthreads();

    const float* sx = sh_x[gid];
    float h0 = 0.f, h1 = 0.f, h2 = 0.f, h3 = 0.f;
#pragma unroll
    for (int k = 0; k < DIN; k += 4) {
        h0 = fmaf(sx[k],     W1[(k)     * H + j], h0);
        h1 = fmaf(sx[k + 1], W1[(k + 1) * H + j], h1);
        h2 = fmaf(sx[k + 2], W1[(k + 2) * H + j], h2);
        h3 = fmaf(sx[k + 3], W1[(k + 3) * H + j], h3);
    }
    float h = ((h0 + h1) + (h2 + h3)) + b1[j];

    float s1 = h, s2 = h * h;
#pragma unroll
    for (int o = 16; o; o >>= 1) {
        s1 += __shfl_xor_sync(~0u, s1, o);
        s2 += __shfl_xor_sync(~0u, s2, o);
    }
    if ((j & 31) == 0) { sh_red[gid][wid] = s1; sh_red[gid][2 + wid] = s2; }
    __syncthreads();
    const float m   = (sh_red[gid][0] + sh_red[gid][1]) * (1.f / H);
    const float e2  = (sh_red[gid][2] + sh_red[gid][3]) * (1.f / H);
    const float inv = rsqrtf(e2 - m * m + LN_EPS);
    float r = (h - m) * inv * g[j] + beta[j];
    r = fmaxf(r, 0.f);
    __syncthreads();
    sh_r[gid][j] = r;
    __syncthreads();

    const float* sr = sh_r[gid];
    float a0 = 0.f, a1 = 0.f, a2v = 0.f, a3 = 0.f;
#pragma unroll
    for (int k = 0; k < H; k += 4) {
        a0  = fmaf(sr[k],     W2[(k)     * H + j], a0);
        a1  = fmaf(sr[k + 1], W2[(k + 1) * H + j], a1);
        a2v = fmaf(sr[k + 2], W2[(k + 2) * H + j], a2v);
        a3  = fmaf(sr[k + 3], W2[(k + 3) * H + j], a3);
    }
    float ad = ((a0 + a1) + (a2v + a3)) + b2[j];

    if (IS_TARGET) {
        g_t_ad[(size_t)row * H + j] = ad;
        float s = ad;
#pragma unroll
        for (int o = 16; o; o >>= 1) s += __shfl_xor_sync(~0u, s, o);
        if ((j & 31) == 0) sh_red[gid][wid] = s;
    } else {
        g_s_ad[(size_t)row * H + j] = ad;
    }
    sh_ad[gid][j] = ad;
    __syncthreads();

    if (IS_TARGET && j == 0) {
        float mt = (sh_red[gid][0] + sh_red[gid][1]) * (1.f / H);
        g_gate[row] = 1.f / (1.f + __expf(-mt));
    }

    const float* sa = sh_ad[gid];
    float p0 = IS_TARGET ? cb[j] : 0.f, p1k = 0.f, p2k = 0.f, p3k = 0.f;
#pragma unroll
    for (int k = 0; k < H; k += 4) {
        p0  = fmaf(sa[k],     cWpart[(k)     * H + j], p0);
        p1k = fmaf(sa[k + 1], cWpart[(k + 1) * H + j], p1k);
        p2k = fmaf(sa[k + 2], cWpart[(k + 2) * H + j], p2k);
        p3k = fmaf(sa[k + 3], cWpart[(k + 3) * H + j], p3k);
    }
    float p = ((p0 + p1k) + (p2k + p3k));

    if (IS_TARGET) g_a[(size_t)row * H + j] = p;
    else           g_u[(size_t)row * H + j] = p;

    float q1 = p, q2 = p * p;
#pragma unroll
    for (int o = 16; o; o >>= 1) {
        q1 += __shfl_xor_sync(~0u, q1, o);
        q2 += __shfl_xor_sync(~0u, q2, o);
    }
    __syncthreads();
    if ((j & 31) == 0) { sh_red[gid][wid] = q1; sh_red[gid][2 + wid] = q2; }
    __syncthreads();
    if (j == 0) {
        if (IS_TARGET) { g_sum_a[row] = sh_red[gid][0] + sh_red[gid][1]; g_sa2[row] = sh_red[gid][2] + sh_red[gid][3]; }
        else           { g_sum_u[row] = sh_red[gid][0] + sh_red[gid][1]; g_su2[row] = sh_red[gid][2] + sh_red[gid][3]; }
    }
}

// ---------------- score kernel: u in regs (single smem read), a in smem, cp.async pipeline ----
__global__ __launch_bounds__(256, 2)
void score_kernel(float* __restrict__ out_scores)
{
    __shared__ __align__(16) float u_sh[2][CH * USTRIDE];
    __shared__ __align__(16) float a_sh[TILE_T][H];

    const int tid = threadIdx.x;
    const int lane = tid & 31;
    const int w = tid >> 5;
    const int tglob = blockIdx.x * TILE_T + w;
    const int b = tglob >> 10;
    const int srow0 = b << 10;

    // stage this warp's a row to shared (warp-uniform data -> broadcast reads later)
    ((float2*)a_sh[w])[lane] = ((const float2*)(g_a + (size_t)tglob * H))[lane];

    const float suma = g_sum_a[tglob];
    const float sqa  = g_sa2[tglob];
    const float simb0 = c_simb[0];

    // prologue: stage chunk 0
    {
        const float4* src = (const float4*)(g_u + (size_t)srow0 * H);
#pragma unroll
        for (int rep = 0; rep < 2; rep++) {
            int f = tid + rep * 256;
            int r = f >> 4, q = f & 15;
            cp16(&u_sh[0][r * USTRIDE + q * 4], src + f);
        }
        asm volatile("cp.async.commit_group;");
    }

    float sumexp = 0.f;
    float* srow_out = out_scores + (size_t)tglob * SS;
    __syncthreads();   // a_sh visible (and aligns warps before pipeline)

    for (int c = 0; c < SS / CH; c++) {
        if (c < SS / CH - 1) {
            const float4* src = (const float4*)(g_u + (size_t)(srow0 + (c + 1) * CH) * H);
            float* dst = u_sh[(c + 1) & 1];
#pragma unroll
            for (int rep = 0; rep < 2; rep++) {
                int f = tid + rep * 256;
                int r = f >> 4, q = f & 15;
                cp16(&dst[r * USTRIDE + q * 4], src + f);
            }
            asm volatile("cp.async.commit_group;");
            asm volatile("cp.async.wait_group 1;");
        } else {
            asm volatile("cp.async.wait_group 0;");
        }
        __syncthreads();

        // load u row for this lane's s ONCE into registers
        const ulonglong2* up2 = (const ulonglong2*)&u_sh[c & 1][lane * USTRIDE];
        ull u2[H / 2];
#pragma unroll
        for (int i = 0; i < H / 4; i++) {
            ulonglong2 v = up2[i];
            u2[2 * i] = v.x; u2[2 * i + 1] = v.y;
        }

        const int sidx = srow0 + c * CH + lane;
        const float su  = g_sum_u[sidx];
        const float squ = g_su2[sidx];

        const ulonglong2* ap2 = (const ulonglong2*)a_sh[w];

        // pass 1: dot(a,u), a via broadcast LDS
        ull d0 = 0ull, d1 = 0ull, d2 = 0ull, d3 = 0ull;
#pragma unroll
        for (int i = 0; i < H / 4; i += 2) {
            ulonglong2 aa = ap2[i];
            ulonglong2 ab = ap2[i + 1];
            d0 = fma2(aa.x, u2[2 * i],     d0);
            d1 = fma2(aa.y, u2[2 * i + 1], d1);
            d2 = fma2(ab.x, u2[2 * i + 2], d2);
            d3 = fma2(ab.y, u2[2 * i + 3], d3);
        }
        float2 f0 = unpack2(d0), f1 = unpack2(d1), f2 = unpack2(d2), f3 = unpack2(d3);
        const float dot = ((f0.x + f0.y) + (f1.x + f1.y)) + ((f2.x + f2.y) + (f3.x + f3.y));

        const float m   = (suma + su) * (1.f / H);
        const float e2  = (sqa + 2.f * dot + squ) * (1.f / H);
        const float inv = rsqrtf(e2 - m * m + LN_EPS);
        const float nm  = -m * inv;
        const ull inv2 = pack2(inv, inv);
        const ull nm2  = pack2(nm, nm);

        // pass 2: fully packed; u from regs, a from broadcast LDS, cg/cb/w packed consts
        ull acca = 0ull, accb = 0ull;
#pragma unroll
        for (int i = 0; i < H / 4; i++) {
            ulonglong2 aa = ap2[i];
            ull p0 = add2(aa.x, u2[2 * i]);
            ull p1 = add2(aa.y, u2[2 * i + 1]);
            ull z0 = fma2(p0, inv2, nm2);
            ull z1 = fma2(p1, inv2, nm2);
            ull y0 = fma2(z0, *(const ull*)&c_cg[4 * i],     *(const ull*)&c_cb[4 * i]);
            ull y1 = fma2(z1, *(const ull*)&c_cg[4 * i + 2], *(const ull*)&c_cb[4 * i + 2]);
            float2 ya = unpack2(y0), yb = unpack2(y1);
            ya.x = fmaxf(ya.x, 0.f); ya.y = fmaxf(ya.y, 0.f);
            yb.x = fmaxf(yb.x, 0.f); yb.y = fmaxf(yb.y, 0.f);
            acca = fma2(pack2(ya.x, ya.y), *(const ull*)&c_w[4 * i],     acca);
            accb = fma2(pack2(yb.x, yb.y), *(const ull*)&c_w[4 * i + 2], accb);
        }
        float2 sa2 = unpack2(acca), sb2 = unpack2(accb);
        const float acc = (sa2.x + sa2.y) + (sb2.x + sb2.y);
        const float score = 1.f / (1.f + __expf(-(acc + simb0)));
        srow_out[c * CH + lane] = score;
        sumexp += __expf(score);

        __syncthreads();   // compute done before next stage overwrites this buffer
    }

#pragma unroll
    for (int o = 16; o; o >>= 1) sumexp += __shfl_xor_sync(~0u, sumexp, o);
    if (lane == 0) g_sumexp[tglob] = sumexp;
}

// ---------------- transfer: 512 threads, 16 warps, each warp covers 64 s; TTG=8 t-rows ----
__global__ __launch_bounds__(512)
void transfer_kernel(const float* __restrict__ scores, float* __restrict__ out_adapted)
{
    __shared__ __align__(16) ull e2_sh[16][32 * TTG];          // 32 KB: duplicated-exp per warp
    __shared__ __align__(16) float red[16 * TTG * H];          // 32 KB: per-warp partials

    const int tid = threadIdx.x;
    const int w = tid >> 5, lane = tid & 31;
    const int tbase = blockIdx.x * TTG;
    const int b = tbase >> 10;
    const int srow0 = b << 10;

    ull acc2[TTG];
#pragma unroll
    for (int t = 0; t < TTG; t++) acc2[t] = 0ull;

    for (int c = 0; c < 2; c++) {
        const int sloc0 = w * 64 + c * 32;

        // lane loads scores for its own s across 8 t, stores duplicated exp
#pragma unroll
        for (int t = 0; t < TTG; t++) {
            float e = __expf(scores[(size_t)(tbase + t) * SS + sloc0 + lane]);
            e2_sh[w][lane * TTG + t] = pack2(e, e);
        }
        __syncwarp();

#pragma unroll 4
        for (int j = 0; j < 32; j += 8) {
            // batch 8 independent s_ad loads (MLP=8)
            ull v[8];
#pragma unroll
            for (int k = 0; k < 8; k++)
                v[k] = *(const ull*)(g_s_ad + (size_t)(srow0 + sloc0 + j + k) * H + 2 * lane);
#pragma unroll
            for (int k = 0; k < 8; k++) {
                const ulonglong2* ep = (const ulonglong2*)&e2_sh[w][(j + k) * TTG];
                ulonglong2 e01 = ep[0], e23 = ep[1], e45 = ep[2], e67 = ep[3];
                acc2[0] = fma2(v[k], e01.x, acc2[0]);
                acc2[1] = fma2(v[k], e01.y, acc2[1]);
                acc2[2] = fma2(v[k], e23.x, acc2[2]);
                acc2[3] = fma2(v[k], e23.y, acc2[3]);
                acc2[4] = fma2(v[k], e45.x, acc2[4]);
                acc2[5] = fma2(v[k], e45.y, acc2[5]);
                acc2[6] = fma2(v[k], e67.x, acc2[6]);
                acc2[7] = fma2(v[k], e67.y, acc2[7]);
            }
        }
        __syncwarp();
    }

    // write partials: warp w, t, h-pair(2*lane)
#pragma unroll
    for (int t = 0; t < TTG; t++)
        *(ull*)&red[(w * TTG + t) * H + 2 * lane] = acc2[t];
    __syncthreads();

    // combine across 16 warps: tid -> (t = tid>>6, h = tid&63)
    const int t = tid >> 6;
    const int hh = tid & 63;
    float s = 0.f;
#pragma unroll
    for (int ww = 0; ww < 16; ww++) s += red[(ww * TTG + t) * H + hh];

    const int tg = tbase + t;
    const float rs = 1.f / g_sumexp[tg];
    const float gt = g_gate[tg];
    const float ta = g_t_ad[(size_t)tg * H + hh];
    out_adapted[(size_t)tg * H + hh] = ta * (1.f - gt) + s * rs * gt;
}

// ---------------- launch ----------------
extern "C" void kernel_launch(void* const* d_in, const int* in_sizes, int n_in,
                              void* d_out, int out_size)
{
    (void)in_sizes; (void)n_in; (void)out_size;
    const float* src   = (const float*)d_in[0];
    const float* tgt   = (const float*)d_in[1];
    const float* sW1   = (const float*)d_in[2];
    const float* sb1   = (const float*)d_in[3];
    const float* sg    = (const float*)d_in[4];
    const float* sbeta = (const float*)d_in[5];
    const float* sW2   = (const float*)d_in[6];
    const float* sb2   = (const float*)d_in[7];
    const float* tW1   = (const float*)d_in[8];
    const float* tb1   = (const float*)d_in[9];
    const float* tg    = (const float*)d_in[10];
    const float* tbeta = (const float*)d_in[11];
    const float* tW2   = (const float*)d_in[12];
    const float* tb2   = (const float*)d_in[13];
    const float* cW    = (const float*)d_in[14];
    const float* cb    = (const float*)d_in[15];
    const float* cg    = (const float*)d_in[16];
    const float* cbeta = (const float*)d_in[17];
    const float* simW  = (const float*)d_in[18];
    const float* simb  = (const float*)d_in[19];

    float* out_adapted = (float*)d_out;                      // (B,T,H)
    float* out_scores  = out_adapted + (size_t)BB * TT * H;  // (B,T,S)

    cudaMemcpyToSymbolAsync(c_cg,   cg,    H * sizeof(float), 0, cudaMemcpyDeviceToDevice, 0);
    cudaMemcpyToSymbolAsync(c_cb,   cbeta, H * sizeof(float), 0, cudaMemcpyDeviceToDevice, 0);
    cudaMemcpyToSymbolAsync(c_w,    simW,  H * sizeof(float), 0, cudaMemcpyDeviceToDevice, 0);
    cudaMemcpyToSymbolAsync(c_simb, simb,  sizeof(float),     0, cudaMemcpyDeviceToDevice, 0);

    adapter_kernel<DS, false><<<BB * SS / 4, 256>>>(src, sW1, sb1, sg, sbeta, sW2, sb2,
                                                    cW + H * H, nullptr);
    adapter_kernel<DT, true><<<BB * TT / 4, 256>>>(tgt, tW1, tb1, tg, tbeta, tW2, tb2,
                                                   cW, cb);
    score_kernel<<<(BB * TT) / TILE_T, 256>>>(out_scores);
    transfer_kernel<<<(BB * TT) / TTG, 512>>>(out_scores, out_adapted);
}